// round 4
// baseline (speedup 1.0000x reference)
#include <cuda_runtime.h>
#include <cuda_bf16.h>

// Problem constants (fixed by the reference)
static constexpr int BN = 262144;   // batch
static constexpr int KN = 3;        // centers per class
static constexpr int DN = 64;       // feature dim
static constexpr float TH_F  = 0.95f;
static constexpr float EPS_F = 1e-12f;

// One warp handles exactly 4 rows; 65536 warps total = BN/4.
static constexpr int GRID = 8192;   // 8192 blocks * 8 warps = 65536 warps

// Global accumulators (zero-initialized at module load; reset by last block each run)
__device__ double g_sum_min    = 0.0;
__device__ double g_sum_masked = 0.0;
__device__ double g_cnt        = 0.0;
__device__ unsigned int g_done = 0u;

__device__ __forceinline__ float dist4(const float4 a, const float4 b) {
    const float d0 = a.x - b.x, d1 = a.y - b.y;
    const float d2 = a.z - b.z, d3 = a.w - b.w;
    return d0 * d0 + d1 * d1 + d2 * d2 + d3 * d3;
}

// 8 lanes per row, 4 rows per warp, single shot.
// lane = r*8 + s: row r (0..3), octant s (0..7).
// Every center LDG.128 warp-wide covers 4 FULL 128B lines (dense wavefronts).
__global__ void __launch_bounds__(256)
dist_kernel(const float4* __restrict__ x4,
            const int*    __restrict__ labels,
            const float4* __restrict__ c4,
            float*        __restrict__ out)
{
    const int lane    = threadIdx.x & 31;
    const int r       = lane >> 3;       // row within warp group (0..3)
    const int s       = lane & 7;        // float4 slot within 128B half-row
    const int warp_id = (blockIdx.x * blockDim.x + threadIdx.x) >> 5;

    const int row = warp_id * 4 + r;     // < BN always (65536*4 == BN)

    // label first: 8 lanes share one address; starts the dependent chain early
    const int lab = __ldg(&labels[row]);

    // x: 2 float4 per lane; each warp LDG = 4 rows x 128B contiguous = dense
    const float4* xb = x4 + (size_t)row * 16 + s;
    const float4 xv0 = __ldcs(xb + 0);
    const float4 xv1 = __ldcs(xb + 8);

    const float4* cb = c4 + (size_t)lab * (KN * (DN / 4)) + s;

    // 3 centers x 2 half-rows, all loads independent -> MLP = 8
    const float4 c00 = __ldg(cb + 0);
    const float4 c01 = __ldg(cb + 8);
    const float4 c10 = __ldg(cb + 16);
    const float4 c11 = __ldg(cb + 24);
    const float4 c20 = __ldg(cb + 32);
    const float4 c21 = __ldg(cb + 40);

    float p0 = dist4(xv0, c00) + dist4(xv1, c01);
    float p1 = dist4(xv0, c10) + dist4(xv1, c11);
    float p2 = dist4(xv0, c20) + dist4(xv1, c21);

    // Reduce within the 8-lane group (xor 1,2,4 never crosses groups)
    #pragma unroll
    for (int o = 1; o < 8; o <<= 1) {
        p0 += __shfl_xor_sync(0xffffffffu, p0, o);
        p1 += __shfl_xor_sync(0xffffffffu, p1, o);
        p2 += __shfl_xor_sync(0xffffffffu, p2, o);
    }

    float acc_min = 0.f, acc_msk = 0.f, acc_cnt = 0.f;
    if (s == 0) {
        // two smallest of three + min
        const float mn  = fminf(fminf(p0, p1), p2);
        const float mx  = fmaxf(fmaxf(p0, p1), p2);
        const float mid = (p0 + p1 + p2) - mn - mx;

        const float a = mn  + EPS_F;
        const float b = mid + EPS_F;
        const float p = a / (a + b);                  // 0 < p <= 0.5
        const float ent = -(p * log2f(p) + (1.f - p) * log2f(1.f - p));

        acc_min = mn;
        if (ent <= TH_F) { acc_msk = mn; acc_cnt = 1.f; }
    }

    // Warp reduce (only lanes with s==0 carry nonzero values)
    #pragma unroll
    for (int o = 16; o > 0; o >>= 1) {
        acc_min += __shfl_xor_sync(0xffffffffu, acc_min, o);
        acc_msk += __shfl_xor_sync(0xffffffffu, acc_msk, o);
        acc_cnt += __shfl_xor_sync(0xffffffffu, acc_cnt, o);
    }

    // Block reduce + one double atomic triple per block
    __shared__ float sm[3][8];
    __shared__ bool  s_last;
    const int wib = threadIdx.x >> 5;
    if (lane == 0) { sm[0][wib] = acc_min; sm[1][wib] = acc_msk; sm[2][wib] = acc_cnt; }
    __syncthreads();

    if (threadIdx.x == 0) {
        float a = 0.f, b = 0.f, c = 0.f;
        #pragma unroll
        for (int i = 0; i < 8; i++) { a += sm[0][i]; b += sm[1][i]; c += sm[2][i]; }
        atomicAdd(&g_sum_min,    (double)a);
        atomicAdd(&g_sum_masked, (double)b);
        atomicAdd(&g_cnt,        (double)c);
        __threadfence();
        const unsigned int ticket = atomicAdd(&g_done, 1u);
        s_last = (ticket == (unsigned int)(GRID - 1));
    }
    __syncthreads();

    // Last block: produce outputs and reset state for the next graph replay
    if (s_last && threadIdx.x == 0) {
        __threadfence();
        const double smn = g_sum_min;
        const double smk = g_sum_masked;
        const double cnt = g_cnt;
        out[0] = (float)(smn / (double)BN);
        out[1] = (float)(smk / cnt);
        g_sum_min = 0.0; g_sum_masked = 0.0; g_cnt = 0.0;
        __threadfence();
        g_done = 0u;
    }
}

extern "C" void kernel_launch(void* const* d_in, const int* in_sizes, int n_in,
                              void* d_out, int out_size) {
    const float* x       = (const float*)d_in[0];   // [B, D] f32
    const int*   labels  = (const int*)  d_in[1];   // [B] i32
    const float* centers = (const float*)d_in[2];   // [C, K, D] f32

    dist_kernel<<<GRID, 256>>>((const float4*)x, labels,
                               (const float4*)centers, (float*)d_out);
}

// round 5
// speedup vs baseline: 1.3916x; 1.3916x over previous
#include <cuda_runtime.h>
#include <cuda_bf16.h>

// Problem constants (fixed by the reference)
static constexpr int BN = 262144;   // batch
static constexpr int KN = 3;        // centers per class
static constexpr int DN = 64;       // feature dim
static constexpr float TH_F  = 0.95f;
static constexpr float EPS_F = 1e-12f;

static constexpr int GRID   = 2048;                 // 2048*8 = 16384 warps
static constexpr int NWARPS = GRID * 256 / 32;      // 16384
static constexpr int ITERS  = BN / 4 / NWARPS;      // 4 row-groups per warp

// Global accumulators (zero-initialized at module load; reset by last block each run)
__device__ double g_sum_min    = 0.0;
__device__ double g_sum_masked = 0.0;
__device__ double g_cnt        = 0.0;
__device__ unsigned int g_done = 0u;

__device__ __forceinline__ float dist4(const float4 a, const float4 b) {
    const float d0 = a.x - b.x, d1 = a.y - b.y;
    const float d2 = a.z - b.z, d3 = a.w - b.w;
    return d0 * d0 + d1 * d1 + d2 * d2 + d3 * d3;
}

// 8 lanes per row, 4 rows per warp-iteration, 4 iterations per warp.
// lane = r*8 + s. Every center LDG.128 warp-wide covers 4 FULL 128B lines.
// All labels are loaded up front so center loads never wait on a fresh LDG chain.
__global__ void __launch_bounds__(256)
dist_kernel(const float4* __restrict__ x4,
            const int*    __restrict__ labels,
            const float4* __restrict__ c4,
            float*        __restrict__ out)
{
    const int lane    = threadIdx.x & 31;
    const int r       = lane >> 3;       // row within group (0..3)
    const int s       = lane & 7;        // float4 slot within 128B half-row
    const int warp_id = (blockIdx.x * blockDim.x + threadIdx.x) >> 5;

    // Prefetch all labels (independent loads, resolve while x streams in)
    int labs[ITERS];
    #pragma unroll
    for (int it = 0; it < ITERS; it++) {
        const int row = (warp_id + it * NWARPS) * 4 + r;
        labs[it] = __ldg(&labels[row]);
    }

    float acc_min = 0.f, acc_msk = 0.f, acc_cnt = 0.f;

    #pragma unroll
    for (int it = 0; it < ITERS; it++) {
        const int grp = warp_id + it * NWARPS;
        const int row = grp * 4 + r;

        // x: 2 float4 per lane; warp LDG = 4 rows x 128B contiguous (dense)
        const float4* xb = x4 + (size_t)row * 16 + s;
        const float4 xv0 = __ldcs(xb + 0);
        const float4 xv1 = __ldcs(xb + 8);

        const float4* cb = c4 + (size_t)labs[it] * (KN * (DN / 4)) + s;

        // 3 centers x 2 half-rows, independent -> MLP 8 within iter (+ across iters)
        const float4 c00 = __ldg(cb + 0);
        const float4 c01 = __ldg(cb + 8);
        const float4 c10 = __ldg(cb + 16);
        const float4 c11 = __ldg(cb + 24);
        const float4 c20 = __ldg(cb + 32);
        const float4 c21 = __ldg(cb + 40);

        float p0 = dist4(xv0, c00) + dist4(xv1, c01);
        float p1 = dist4(xv0, c10) + dist4(xv1, c11);
        float p2 = dist4(xv0, c20) + dist4(xv1, c21);

        // Reduce within the 8-lane group (xor 1,2,4 never crosses groups)
        #pragma unroll
        for (int o = 1; o < 8; o <<= 1) {
            p0 += __shfl_xor_sync(0xffffffffu, p0, o);
            p1 += __shfl_xor_sync(0xffffffffu, p1, o);
            p2 += __shfl_xor_sync(0xffffffffu, p2, o);
        }

        if (s == 0) {
            // two smallest of three + min
            const float mn  = fminf(fminf(p0, p1), p2);
            const float mx  = fmaxf(fmaxf(p0, p1), p2);
            const float mid = (p0 + p1 + p2) - mn - mx;

            const float a = mn  + EPS_F;
            const float b = mid + EPS_F;
            const float p = a / (a + b);                  // 0 < p <= 0.5
            const float ent = -(p * log2f(p) + (1.f - p) * log2f(1.f - p));

            acc_min += mn;
            if (ent <= TH_F) { acc_msk += mn; acc_cnt += 1.f; }
        }
    }

    // Warp reduce (only s==0 lanes carry nonzero values)
    #pragma unroll
    for (int o = 16; o > 0; o >>= 1) {
        acc_min += __shfl_xor_sync(0xffffffffu, acc_min, o);
        acc_msk += __shfl_xor_sync(0xffffffffu, acc_msk, o);
        acc_cnt += __shfl_xor_sync(0xffffffffu, acc_cnt, o);
    }

    // Block reduce + one double atomic triple per block
    __shared__ float sm[3][8];
    __shared__ bool  s_last;
    const int wib = threadIdx.x >> 5;
    if (lane == 0) { sm[0][wib] = acc_min; sm[1][wib] = acc_msk; sm[2][wib] = acc_cnt; }
    __syncthreads();

    if (threadIdx.x == 0) {
        float a = 0.f, b = 0.f, c = 0.f;
        #pragma unroll
        for (int i = 0; i < 8; i++) { a += sm[0][i]; b += sm[1][i]; c += sm[2][i]; }
        atomicAdd(&g_sum_min,    (double)a);
        atomicAdd(&g_sum_masked, (double)b);
        atomicAdd(&g_cnt,        (double)c);
        __threadfence();
        const unsigned int ticket = atomicAdd(&g_done, 1u);
        s_last = (ticket == (unsigned int)(GRID - 1));
    }
    __syncthreads();

    // Last block: produce outputs and reset state for the next graph replay
    if (s_last && threadIdx.x == 0) {
        __threadfence();
        const double smn = g_sum_min;
        const double smk = g_sum_masked;
        const double cnt = g_cnt;
        out[0] = (float)(smn / (double)BN);
        out[1] = (float)(smk / cnt);
        g_sum_min = 0.0; g_sum_masked = 0.0; g_cnt = 0.0;
        __threadfence();
        g_done = 0u;
    }
}

extern "C" void kernel_launch(void* const* d_in, const int* in_sizes, int n_in,
                              void* d_out, int out_size) {
    const float* x       = (const float*)d_in[0];   // [B, D] f32
    const int*   labels  = (const int*)  d_in[1];   // [B] i32
    const float* centers = (const float*)d_in[2];   // [C, K, D] f32

    dist_kernel<<<GRID, 256>>>((const float4*)x, labels,
                               (const float4*)centers, (float*)d_out);
}